// round 8
// baseline (speedup 1.0000x reference)
#include <cuda_runtime.h>
#include <cuda_bf16.h>
#include <math.h>
#include <cstdint>

#define TT  30
#define BBN 2048
#define DD  256
#define DHH 128

typedef unsigned long long u64;
typedef unsigned int       u32;
typedef unsigned short     u16;

#if defined(__CUDA_ARCH_FEAT_SM103_ALL) || defined(__CUDA_ARCH_FEAT_SM100_ALL) || defined(__CUDA_ARCH_FEAT_SM101_ALL)
#define USE_TCGEN05 1
#else
#define USE_TCGEN05 0
#endif

// Fixed softmax shift 64 (proven R7): no overflow (needs s>152), FTZ-dropped
// terms are >=55 e-folds below any row max, log(0) impossible via clamp.
#define SOFT_SHIFT 64.0f
#define L2E        1.4426950408889634f
#define SHIFT_L2E  (-64.0f * 1.4426950408889634f)

// ---------------------------------------------------------------------------
__device__ float g_lse29[BBN];
__device__ float g_nce[TT * 16];
__device__ u64   g_win[BBN];
__device__ int   g_done = 0;
__device__ u16   g_repB[16 * 32768];       // per 128-col chunk: [hi 16K][lo 16K], swizzled
__device__ u16   g_WB[TT * 2 * 32768];     // per (t,khalf): [hi][lo] W^T tile, swizzled
__device__ u16   g_A29B[16 * 32768];       // per 128-row block: [hi][lo] A29, swizzled

// ---------------------------------------------------------------------------
__device__ __forceinline__ u16 f2bu(float f) {
    __nv_bfloat16 b = __float2bfloat16(f);
    return reinterpret_cast<u16&>(b);
}
__device__ __forceinline__ float b2f(u16 u) {
    __nv_bfloat16 b = reinterpret_cast<__nv_bfloat16&>(u);
    return __bfloat162float(b);
}
__device__ __forceinline__ int swz_idx(int m, int k) {
    int byte = (((m >> 3) + ((k >> 6) << 4)) << 10) + ((m & 7) << 7) + ((k & 63) << 1);
    byte ^= (byte >> 3) & 0x70;
    return byte >> 1;
}
__device__ __forceinline__ float ex2f(float x) {
    float r; asm("ex2.approx.ftz.f32 %0, %1;" : "=f"(r) : "f"(x)); return r;
}

// ---------------------------------------------------------------------------
__global__ void k_pre_rep(const float* __restrict__ rep) {
    int idx = blockIdx.x * blockDim.x + threadIdx.x;   // c*128 + k
    int c = idx >> 7, k = idx & 127;
    float v = rep[idx];
    u16 hi = f2bu(v);
    u16 lo = f2bu(v - b2f(hi));
    int cb = c >> 7, cl = c & 127;
    g_repB[cb * 32768 + swz_idx(cl, k)]         = hi;
    g_repB[cb * 32768 + 16384 + swz_idx(cl, k)] = lo;
    if (idx < BBN) g_win[idx] = 0ULL;
}

__global__ void k_pre_w(const float* __restrict__ W) {
    int idx = blockIdx.x * blockDim.x + threadIdx.x;
    int t = idx / (DD * DHH);
    int r = idx - t * DD * DHH;
    int d = r / DHH, h = r - d * DHH;
    float v = W[idx];
    u16 hi = f2bu(v);
    u16 lo = f2bu(v - b2f(hi));
    int half = d >> 7, kl = d & 127;
    int base = t * 65536 + half * 32768;
    g_WB[base + swz_idx(h, kl)]         = hi;
    g_WB[base + 16384 + swz_idx(h, kl)] = lo;
}

#if USE_TCGEN05
// ===========================================================================
__device__ __forceinline__ u32 elect_one_pred() {
    u32 pred;
    asm volatile("{\n\t.reg .pred p;\n\telect.sync _|p, 0xFFFFFFFF;\n\tselp.b32 %0, 1, 0, p;\n\t}" : "=r"(pred));
    return pred;
}
__device__ __forceinline__ u32 smem_to_u32(const void* p) {
    u32 a;
    asm("{ .reg .u64 t; cvta.to.shared.u64 t, %1; cvt.u32.u64 %0, t; }" : "=r"(a) : "l"(p));
    return a;
}
#define TCGEN05_ALLOC(sa, n) \
    asm volatile("tcgen05.alloc.cta_group::1.sync.aligned.shared::cta.b32 [%0], %1;" :: "r"((u32)(sa)), "r"((u32)(n)) : "memory")
#define TCGEN05_DEALLOC(ta, n) \
    asm volatile("tcgen05.dealloc.cta_group::1.sync.aligned.b32 %0, %1;" :: "r"(ta), "r"((u32)(n)))
#define TCGEN05_RELINQ() \
    asm volatile("tcgen05.relinquish_alloc_permit.cta_group::1.sync.aligned;")
#define TCGEN05_COMMIT(mb) \
    asm volatile("tcgen05.commit.cta_group::1.mbarrier::arrive::one.shared::cluster.b64 [%0];" :: "r"((u32)(mb)) : "memory")
#define TCGEN05_FENCE_BEFORE()  asm volatile("tcgen05.fence::before_thread_sync;" ::: "memory")
#define TCGEN05_FENCE_AFTER()   asm volatile("tcgen05.fence::after_thread_sync;" ::: "memory")
#define TCGEN05_WAIT_LD()       asm volatile("tcgen05.wait::ld.sync.aligned;" ::: "memory")
#define FENCE_PROXY()           asm volatile("fence.proxy.async.shared::cta;" ::: "memory")
#define MBARRIER_INIT(mb, cnt) \
    asm volatile("mbarrier.init.shared.b64 [%0], %1;" :: "r"((u32)(mb)), "r"((u32)(cnt)) : "memory")
#define MBARRIER_INVAL(mb) \
    asm volatile("mbarrier.inval.shared.b64 [%0];" :: "r"((u32)(mb)) : "memory")
#define MBARRIER_WAIT_PARITY(mb, ph) do {                                          \
    u32 _m = (u32)(mb); u32 _p = (u32)(ph); u32 _d;                                \
    asm volatile("{\n\t.reg .pred p;\n\t"                                          \
        "mbarrier.try_wait.parity.acquire.cta.shared::cta.b64 p, [%1], %2;\n\t"    \
        "selp.b32 %0, 1, 0, p;\n\t}" : "=r"(_d) : "r"(_m), "r"(_p) : "memory");    \
    if (!_d) {                                                                     \
        asm volatile("{\n\t.reg .pred P1;\n\t"                                     \
        "WL_%=:\n\t"                                                               \
        "mbarrier.try_wait.parity.acquire.cta.shared::cta.b64 P1, [%0], %1, 0x989680;\n\t" \
        "@P1 bra.uni WD_%=;\n\t"                                                   \
        "bra.uni WL_%=;\n\t"                                                       \
        "WD_%=:\n\t}" :: "r"(_m), "r"(_p) : "memory");                             \
    }                                                                              \
} while (0)

#define TCGEN05_LD_32X32B_X32(r, ta) \
    asm volatile( \
        "tcgen05.ld.sync.aligned.32x32b.x32.b32 " \
        "{%0, %1, %2, %3, %4, %5, %6, %7, " \
        " %8, %9, %10, %11, %12, %13, %14, %15, " \
        " %16, %17, %18, %19, %20, %21, %22, %23, " \
        " %24, %25, %26, %27, %28, %29, %30, %31}, [%32];" \
        : "=r"((r)[0]),  "=r"((r)[1]),  "=r"((r)[2]),  "=r"((r)[3]), \
          "=r"((r)[4]),  "=r"((r)[5]),  "=r"((r)[6]),  "=r"((r)[7]), \
          "=r"((r)[8]),  "=r"((r)[9]),  "=r"((r)[10]), "=r"((r)[11]), \
          "=r"((r)[12]), "=r"((r)[13]), "=r"((r)[14]), "=r"((r)[15]), \
          "=r"((r)[16]), "=r"((r)[17]), "=r"((r)[18]), "=r"((r)[19]), \
          "=r"((r)[20]), "=r"((r)[21]), "=r"((r)[22]), "=r"((r)[23]), \
          "=r"((r)[24]), "=r"((r)[25]), "=r"((r)[26]), "=r"((r)[27]), \
          "=r"((r)[28]), "=r"((r)[29]), "=r"((r)[30]), "=r"((r)[31]) \
        : "r"(ta))

__device__ __forceinline__ void mma_f16_ss(u32 d, u64 ad, u64 bd, u32 idesc, u32 en) {
    asm volatile(
        "{\n\t.reg .pred p;\n\tsetp.ne.u32 p, %5, 0;\n\t"
        "tcgen05.mma.cta_group::1.kind::f16 [%0], %1, %2, %3, {%4, %4, %4, %4}, p;\n\t}"
        :: "r"(d), "l"(ad), "l"(bd), "r"(idesc), "r"(0u), "r"(en) : "memory");
}

static constexpr u64 DESC_BASE =
    (u64(2) << 61) | (u64(1) << 46) | (u64(64) << 32) | (u64(1) << 16);
#define MK_DESC(a) (DESC_BASE | ((u64)((a) >> 4) & 0x3FFF))
#define IDESC 0x8200490u     // F32 accum, BF16xBF16, M=128, N=128

__device__ __forceinline__ void mma_pass8(u32 d, u64 ad, u64 bd, u32 en0) {
#pragma unroll
    for (int j = 0; j < 8; ++j) {
        u64 off = (u64)((j >> 2) * 1024 + (j & 3) * 2);
        mma_f16_ss(d, ad + off, bd + off, IDESC, j == 0 ? en0 : 1u);
    }
}

__device__ __forceinline__ void copy32k(char* dst, const void* src, int tid) {
    const float4* s = (const float4*)src;
    float4* d = (float4*)dst;
#pragma unroll
    for (int i = 0; i < 8; ++i) d[tid + i * 256] = s[tid + i * 256];
}
#endif  // USE_TCGEN05

// ---------------------------------------------------------------------------
#define SM_TMEMPTR 0
#define SM_MG      8
#define SM_FS0     16
#define SM_DIAG    64        // 128 f32
#define SM_MS      576       // 256 f32
#define SM_RED     1600      // 4 f32
#define SM_R1      4096      // 32KB: E-hi / A-hi
#define SM_R2      36864     // 32KB
#define SM_R3      69632     // 32KB
#define SMEM_MAIN  102400

#define SA_TMEMPTR 0
#define SA_MB      8
#define SA_LAST    16
#define SA_LSE     64
#define SA_RH      1024
#define SA_RL      33792
#define SA_AH      66560
#define SA_AL      99328
#define SMEM_ACC2  132096

#if USE_TCGEN05
__device__ __forceinline__ void stage_E(const float* __restrict__ Et, int base_b, int dk,
                                        char* smc, int tid) {
    int row = tid >> 1;
    int cs  = (tid & 1) * 64;
    const float4* src = (const float4*)(Et + (size_t)(base_b + row) * DD + dk + cs);
    u16* hb = (u16*)(smc + SM_R1);
#pragma unroll
    for (int q = 0; q < 16; ++q) {
        float4 v = src[q];
        int k = cs + q * 4;
        uint2 hw = make_uint2((u32)f2bu(v.x) | ((u32)f2bu(v.y) << 16),
                              (u32)f2bu(v.z) | ((u32)f2bu(v.w) << 16));
        *(uint2*)(hb + swz_idx(row, k)) = hw;
    }
}
#endif

// ---------------------------------------------------------------------------
// Main fused kernel: occupancy 2. TMEM 256 cols/CTA: A at tb+0..127,
// single S buffer at tb+128..255 (LDTM+sync strictly precede next MMA).
// ---------------------------------------------------------------------------
__global__ void __launch_bounds__(256, 2)
k_main2(const float* __restrict__ E) {
    extern __shared__ char smc[];
#if USE_TCGEN05
    const u32 sb = smem_to_u32(smc);
    float* sDiag = (float*)(smc + SM_DIAG);
    float* sMS   = (float*)(smc + SM_MS);
    float* sRed  = (float*)(smc + SM_RED);

    const int t      = blockIdx.y;
    const int rb     = blockIdx.x;
    const int base_b = rb * 128;
    const int tid    = threadIdx.x;
    const int wid    = tid >> 5;
    const int lane   = tid & 31;
    const int sub    = wid & 3;
    const int chalf  = wid >> 2;
    const int r_loc  = sub * 32 + lane;

    const float* Et = E + (size_t)t * BBN * DD;

    if (wid == 0) TCGEN05_ALLOC(sb + SM_TMEMPTR, 256);
    if (tid == 0) {
        MBARRIER_INIT(sb + SM_MG,  1);
        MBARRIER_INIT(sb + SM_FS0, 1);
    }
    __syncthreads();
    u32 tb;
    asm volatile("ld.shared.b32 %0, [%1];" : "=r"(tb) : "r"(sb + SM_TMEMPTR));

    const u64 dR1 = MK_DESC(sb + SM_R1);
    const u64 dR2 = MK_DESC(sb + SM_R2);
    const u64 dR3 = MK_DESC(sb + SM_R3);

    // ------------- GEMM1 (2-pass): A = Eh·(Wh+Wl), two K-halves -----------
#pragma unroll
    for (int kh = 0; kh < 2; ++kh) {
        if (kh == 1) MBARRIER_WAIT_PARITY(sb + SM_MG, 0);
        copy32k(smc + SM_R2, g_WB + t * 65536 + kh * 32768, tid);
        copy32k(smc + SM_R3, g_WB + t * 65536 + kh * 32768 + 16384, tid);
        stage_E(Et, base_b, kh * 128, smc, tid);
        FENCE_PROXY();
        __syncthreads();
        if (wid == 0 && elect_one_pred()) {
            mma_pass8(tb, dR1, dR2, kh == 0 ? 0u : 1u);
            mma_pass8(tb, dR1, dR3, 1u);
            TCGEN05_COMMIT(sb + SM_MG);
        }
    }
    MBARRIER_WAIT_PARITY(sb + SM_MG, 1);
    TCGEN05_FENCE_AFTER();
    __syncthreads();

    // ------------- A epilogue: TMEM -> A-hi swizzled in R1 ----------------
    {
        u32 a0[32], a1[32];
        TCGEN05_LD_32X32B_X32(a0, tb + chalf * 64);
        TCGEN05_LD_32X32B_X32(a1, tb + chalf * 64 + 32);
        TCGEN05_WAIT_LD();
        u16* hb = (u16*)(smc + SM_R1);
#pragma unroll
        for (int q = 0; q < 8; ++q) {
            int k0 = chalf * 64 + q * 4;
            float v0 = __uint_as_float(a0[4 * q]),     v1 = __uint_as_float(a0[4 * q + 1]);
            float v2 = __uint_as_float(a0[4 * q + 2]), v3 = __uint_as_float(a0[4 * q + 3]);
            *(uint2*)(hb + swz_idx(r_loc, k0)) =
                make_uint2((u32)f2bu(v0) | ((u32)f2bu(v1) << 16),
                           (u32)f2bu(v2) | ((u32)f2bu(v3) << 16));
            int k1 = k0 + 32;
            float w0 = __uint_as_float(a1[4 * q]),     w1 = __uint_as_float(a1[4 * q + 1]);
            float w2 = __uint_as_float(a1[4 * q + 2]), w3 = __uint_as_float(a1[4 * q + 3]);
            *(uint2*)(hb + swz_idx(r_loc, k1)) =
                make_uint2((u32)f2bu(w0) | ((u32)f2bu(w1) << 16),
                           (u32)f2bu(w2) | ((u32)f2bu(w3) << 16));
        }
        if (t == TT - 1) {
            u16* gh = g_A29B + rb * 32768;
            u16* gl = gh + 16384;
#pragma unroll
            for (int j = 0; j < 32; ++j) {
                float v = __uint_as_float(a0[j]);
                int k = chalf * 64 + j;
                u16 hi = f2bu(v);
                gh[swz_idx(r_loc, k)] = hi;
                gl[swz_idx(r_loc, k)] = f2bu(v - b2f(hi));
                float w = __uint_as_float(a1[j]);
                int kk = k + 32;
                u16 hi2 = f2bu(w);
                gh[swz_idx(r_loc, kk)] = hi2;
                gl[swz_idx(r_loc, kk)] = f2bu(w - b2f(hi2));
            }
        }
        TCGEN05_FENCE_BEFORE();
        FENCE_PROXY();
    }

    // ------------- GEMM2: 16 chunks of 128 cols, single S buffer ----------
    copy32k(smc + SM_R2, g_repB, tid);       // chunk 0 (hi only)
    FENCE_PROXY();
    __syncthreads();
    if (wid == 0 && elect_one_pred()) {
        mma_pass8(tb + 128, dR1, dR2, 0u);
        TCGEN05_COMMIT(sb + SM_FS0);
    }

    float acc0 = 0.0f, acc1 = 0.0f, acc2 = 0.0f, acc3 = 0.0f;

    for (int i = 0; i < 16; ++i) {
        if (i < 15) {   // stage next chunk's B into the other smem buffer
            copy32k(smc + ((i & 1) ? SM_R2 : SM_R3), g_repB + (i + 1) * 32768, tid);
            FENCE_PROXY();
        }
        MBARRIER_WAIT_PARITY(sb + SM_FS0, i & 1);
        TCGEN05_FENCE_AFTER();

        u32 v0[32], v1[32];
        TCGEN05_LD_32X32B_X32(v0, tb + 128 + chalf * 64);
        TCGEN05_LD_32X32B_X32(v1, tb + 128 + chalf * 64 + 32);
        TCGEN05_WAIT_LD();
        TCGEN05_FENCE_BEFORE();
        __syncthreads();   // all warps drained S; B(i+1) staged

        if (i < 15 && wid == 0 && elect_one_pred()) {
            mma_pass8(tb + 128, dR1, (i & 1) ? dR2 : dR3, 0u);
            TCGEN05_COMMIT(sb + SM_FS0);
        }

        if (i == rb) {   // diagonal capture
            int jd = r_loc - chalf * 64;
#pragma unroll
            for (int j = 0; j < 32; ++j) {
                if (j == jd)      sDiag[r_loc] = __uint_as_float(v0[j]);
                if (j + 32 == jd) sDiag[r_loc] = __uint_as_float(v1[j]);
            }
        }

        // sum += exp(s - 64); 4 independent chains (overlaps next MMA)
#pragma unroll
        for (int j = 0; j < 32; j += 4) {
            acc0 += ex2f(fmaf(__uint_as_float(v0[j]),     L2E, SHIFT_L2E));
            acc1 += ex2f(fmaf(__uint_as_float(v0[j + 1]), L2E, SHIFT_L2E));
            acc2 += ex2f(fmaf(__uint_as_float(v0[j + 2]), L2E, SHIFT_L2E));
            acc3 += ex2f(fmaf(__uint_as_float(v0[j + 3]), L2E, SHIFT_L2E));
        }
#pragma unroll
        for (int j = 0; j < 32; j += 4) {
            acc0 += ex2f(fmaf(__uint_as_float(v1[j]),     L2E, SHIFT_L2E));
            acc1 += ex2f(fmaf(__uint_as_float(v1[j + 1]), L2E, SHIFT_L2E));
            acc2 += ex2f(fmaf(__uint_as_float(v1[j + 2]), L2E, SHIFT_L2E));
            acc3 += ex2f(fmaf(__uint_as_float(v1[j + 3]), L2E, SHIFT_L2E));
        }
    }
    __syncthreads();

    sMS[r_loc * 2 + chalf] = (acc0 + acc1) + (acc2 + acc3);
    __syncthreads();

    if (tid < 128) {
        float sum = fmaxf(sMS[tid * 2] + sMS[tid * 2 + 1], 1e-35f);
        float lse = SOFT_SHIFT + __logf(sum);
        if (t == TT - 1) g_lse29[base_b + tid] = lse;
        float part = sDiag[tid] - lse;
#pragma unroll
        for (int o = 1; o < 32; o <<= 1)
            part += __shfl_xor_sync(0xffffffffu, part, o);
        if ((tid & 31) == 0) sRed[tid >> 5] = part;
    }
    __syncthreads();
    if (tid == 0)
        g_nce[t * 16 + rb] = sRed[0] + sRed[1] + sRed[2] + sRed[3];

    if (tid == 0) {
        MBARRIER_INVAL(sb + SM_MG);
        MBARRIER_INVAL(sb + SM_FS0);
    }
    __syncthreads();
    if (wid == 0) {
        TCGEN05_RELINQ();
        TCGEN05_DEALLOC(tb, 256);
    }
#endif
}

// ---------------------------------------------------------------------------
// Accuracy pass (t=29) on tensor cores + fused finalize (unchanged, proven)
// ---------------------------------------------------------------------------
__global__ void __launch_bounds__(256, 1)
k_acc2(float* __restrict__ out, int out_size) {
    extern __shared__ char smc[];
#if USE_TCGEN05
    const u32 sb = smem_to_u32(smc);
    float* sLse = (float*)(smc + SA_LSE);
    int*   sLast = (int*)(smc + SA_LAST);

    const int cb  = blockIdx.x;
    const int bb  = blockIdx.y;
    const int tid = threadIdx.x;
    const int wid = tid >> 5;
    const int lane = tid & 31;
    const int sub = wid & 3;
    const int chalf = wid >> 2;
    const int r_loc = sub * 32 + lane;

    if (wid == 0) TCGEN05_ALLOC(sb + SA_TMEMPTR, 128);
    if (tid == 0) MBARRIER_INIT(sb + SA_MB, 1);
    __syncthreads();
    u32 tb;
    asm volatile("ld.shared.b32 %0, [%1];" : "=r"(tb) : "r"(sb + SA_TMEMPTR));

    copy32k(smc + SA_RH, g_repB + cb * 32768, tid);
    copy32k(smc + SA_RL, g_repB + cb * 32768 + 16384, tid);
    copy32k(smc + SA_AH, g_A29B + bb * 32768, tid);
    copy32k(smc + SA_AL, g_A29B + bb * 32768 + 16384, tid);
    if (tid < 128) sLse[tid] = g_lse29[bb * 128 + tid];
    FENCE_PROXY();
    __syncthreads();

    if (wid == 0 && elect_one_pred()) {
        u64 dRH = MK_DESC(sb + SA_RH), dRL = MK_DESC(sb + SA_RL);
        u64 dAH = MK_DESC(sb + SA_AH), dAL = MK_DESC(sb + SA_AL);
        mma_pass8(tb, dRH, dAH, 0u);
        mma_pass8(tb, dRH, dAL, 1u);
        mma_pass8(tb, dRL, dAH, 1u);
        TCGEN05_COMMIT(sb + SA_MB);
    }
    MBARRIER_WAIT_PARITY(sb + SA_MB, 0);
    TCGEN05_FENCE_AFTER();

    u32 v0[32], v1[32];
    TCGEN05_LD_32X32B_X32(v0, tb + chalf * 64);
    TCGEN05_LD_32X32B_X32(v1, tb + chalf * 64 + 32);
    TCGEN05_WAIT_LD();

    int c = cb * 128 + r_loc;
    u64 best = 0ULL;
#pragma unroll
    for (int j = 0; j < 32; ++j) {
        float v = __uint_as_float(v0[j]) - sLse[chalf * 64 + j];
        u32 u = __float_as_uint(v);
        u = (u & 0x80000000u) ? ~u : (u | 0x80000000u);
        u64 key = ((u64)u << 32) | (u32)(bb * 128 + chalf * 64 + j);
        if (key > best) best = key;
    }
#pragma unroll
    for (int j = 0; j < 32; ++j) {
        float v = __uint_as_float(v1[j]) - sLse[chalf * 64 + 32 + j];
        u32 u = __float_as_uint(v);
        u = (u & 0x80000000u) ? ~u : (u | 0x80000000u);
        u64 key = ((u64)u << 32) | (u32)(bb * 128 + chalf * 64 + 32 + j);
        if (key > best) best = key;
    }
    atomicMax(&g_win[c], best);

    TCGEN05_FENCE_BEFORE();
    __syncthreads();
    if (tid == 0) MBARRIER_INVAL(sb + SA_MB);
    __syncthreads();
    if (wid == 0) {
        TCGEN05_RELINQ();
        TCGEN05_DEALLOC(tb, 128);
    }

    __threadfence();
    if (tid == 0) {
        int done = atomicAdd(&g_done, 1);
        *sLast = (done == gridDim.x * gridDim.y - 1);
    }
    __syncthreads();
    if (*sLast) {
        __shared__ double rd[256];
        __shared__ int    ri[256];
        int cnt = 0;
        for (int cc = tid; cc < BBN; cc += 256)
            cnt += ((u32)(g_win[cc] & 0xffffffffULL) == (u32)cc);
        double sum = 0.0;
        for (int i = tid; i < TT * 16; i += 256) sum += (double)g_nce[i];
        rd[tid] = sum; ri[tid] = cnt;
        __syncthreads();
        for (int st = 128; st > 0; st >>= 1) {
            if (tid < st) { rd[tid] += rd[tid + st]; ri[tid] += ri[tid + st]; }
            __syncthreads();
        }
        if (tid == 0) {
            out[0] = (float)ri[0] / (float)BBN;
            out[1] = (float)(rd[0] / (-(double)(BBN * TT)));
            out[2] = (float)BBN;
            out[3] = (float)(BBN * TT);
            for (int i = 4; i < out_size; ++i) out[i] = 0.0f;
            g_done = 0;
        }
    }
#endif
}

// ---------------------------------------------------------------------------
extern "C" void kernel_launch(void* const* d_in, const int* in_sizes, int n_in,
                              void* d_out, int out_size) {
    const float* E   = (const float*)d_in[0];
    const float* rep = (const float*)d_in[1];
    const float* W   = (const float*)d_in[2];
    // d_in[3] = Wk_b: row-constant shift, cancels in both softmaxes
    float* out = (float*)d_out;

    cudaFuncSetAttribute(k_main2, cudaFuncAttributeMaxDynamicSharedMemorySize, SMEM_MAIN);
    cudaFuncSetAttribute(k_acc2,  cudaFuncAttributeMaxDynamicSharedMemorySize, SMEM_ACC2);

    k_pre_rep<<<(BBN * DHH) / 256, 256>>>(rep);
    k_pre_w<<<(TT * DD * DHH) / 256, 256>>>(W);

    dim3 g2(16, TT);
    k_main2<<<g2, 256, SMEM_MAIN>>>(E);

    dim3 g3(16, 16);
    k_acc2<<<g3, 256, SMEM_ACC2>>>(out, out_size);
}